// round 8
// baseline (speedup 1.0000x reference)
#include <cuda_runtime.h>
#include <math.h>

#define NN   32768
#define GG   256
#define NPGC 128
#define EE   262144
#define DD   256

// ---------------- scratch (static device globals; no runtime alloc) --------
__device__ int   g_is64;
__device__ int   g_src[EE];
__device__ int   g_dst[EE];
__device__ int   g_cnt[NN];
__device__ int   g_fill[NN];
__device__ int   g_rowptr[NN + 1];
__device__ int   g_srcidx[EE];
__device__ float g_coef[EE];
__device__ float g_dinv[NN];
__device__ float g_B0[NN * DD];
__device__ float g_B1[NN * DD];
__device__ float g_B2[NN * DD];

// ---------------- edge dtype probe + extraction -----------------------------
// JAX without x64 silently stores "int64" edge_index as int32. Probe: read the
// first 2048 words as int64; genuine int64 node ids are all in [0, NN).
// int32 data misread as int64 gives lo + hi*2^32, far out of range.
__global__ void k_detect(const long long* __restrict__ ei) {
    __shared__ int ok;
    if (threadIdx.x == 0) ok = 1;
    __syncthreads();
    for (int idx = threadIdx.x; idx < 2048; idx += 256) {
        long long v = ei[idx];   // 16 KB read; buffer >= 2 MB either way
        if (v < 0 || v >= NN) ok = 0;
    }
    __syncthreads();
    if (threadIdx.x == 0) g_is64 = ok;
}

__global__ void k_extract(const void* __restrict__ eiraw) {
    int e = blockIdx.x * blockDim.x + threadIdx.x;
    if (e >= EE) return;
    int src, dst;
    if (g_is64) {
        const long long* p = (const long long*)eiraw;
        src = (int)p[e];
        dst = (int)p[EE + e];
    } else {
        const int* p = (const int*)eiraw;
        src = p[e];
        dst = p[EE + e];
    }
    g_src[e] = src & (NN - 1);   // trap-insurance mask (NN is a power of 2)
    g_dst[e] = dst & (NN - 1);
}

// ---------------- CSR build -------------------------------------------------
__global__ void k_zero() {
    int i = blockIdx.x * blockDim.x + threadIdx.x;
    if (i < NN) { g_cnt[i] = 0; g_fill[i] = 0; }
}

__global__ void k_count() {
    int e = blockIdx.x * blockDim.x + threadIdx.x;
    if (e < EE) atomicAdd(&g_cnt[g_dst[e]], 1);
}

// single block, 1024 threads, each owns 32 consecutive entries
__global__ void k_scan() {
    __shared__ int ssum[1024];
    int t = threadIdx.x;
    int base = t * 32;
    int loc[32];
    int s = 0;
#pragma unroll
    for (int i = 0; i < 32; i++) {
        int c = g_cnt[base + i];
        loc[i] = s;
        s += c;
        g_dinv[base + i] = rsqrtf((float)c + 1.0f);
    }
    ssum[t] = s;
    __syncthreads();
    for (int off = 1; off < 1024; off <<= 1) {
        int v = 0;
        if (t >= off) v = ssum[t - off];
        __syncthreads();
        if (t >= off) ssum[t] += v;
        __syncthreads();
    }
    int excl = (t == 0) ? 0 : ssum[t - 1];
#pragma unroll
    for (int i = 0; i < 32; i++) g_rowptr[base + i] = excl + loc[i];
    if (t == 1023) g_rowptr[NN] = ssum[1023];
}

__global__ void k_fill() {
    int e = blockIdx.x * blockDim.x + threadIdx.x;
    if (e >= EE) return;
    int src = g_src[e];
    int dst = g_dst[e];
    int pos = g_rowptr[dst] + atomicAdd(&g_fill[dst], 1);
    g_srcidx[pos] = src;
    g_coef[pos]   = g_dinv[src];
}

// ---------------- SGEMM: g_B0[M,256] = A[M,256] @ W[256,256] ----------------
// BM=128, BN=128, BK=16, 256 threads, 8x8 per thread
// SRC: 0 = external pointer, 1 = g_B1
template <int SRC>
__global__ void __launch_bounds__(256) k_gemm(const float* __restrict__ Aext,
                                              const float* __restrict__ W) {
    __shared__ float As[16][128];
    __shared__ float Bs[16][128];
    int tid = threadIdx.x;
    int bx = blockIdx.x;              // 0..1  (col tile)
    int by = blockIdx.y;              // 0..255 (row tile)
    int tx = tid & 15, ty = tid >> 4;
    float acc[8][8] = {};
    const float* A = (SRC == 0) ? Aext : (const float*)g_B1;
    const float* Ab = A + (size_t)by * 128 * DD;
    const float* Wb = W + bx * 128;

    for (int k0 = 0; k0 < DD; k0 += 16) {
#pragma unroll
        for (int l = 0; l < 2; l++) {
            int idx = tid + l * 256;          // 0..511
            int row = idx >> 2;               // 0..127
            int c4  = (idx & 3) * 4;          // 0,4,8,12
            float4 v = *(const float4*)(Ab + row * DD + k0 + c4);
            As[c4 + 0][row] = v.x; As[c4 + 1][row] = v.y;
            As[c4 + 2][row] = v.z; As[c4 + 3][row] = v.w;
        }
#pragma unroll
        for (int l = 0; l < 2; l++) {
            int idx = tid + l * 256;
            int kk = idx >> 5;                // 0..15
            int n4 = (idx & 31) * 4;          // 0..124
            *(float4*)(&Bs[kk][n4]) = *(const float4*)(Wb + (k0 + kk) * DD + n4);
        }
        __syncthreads();
#pragma unroll
        for (int kk = 0; kk < 16; kk++) {
            float a[8], b[8];
            *(float4*)(a)     = *(float4*)(&As[kk][ty * 8]);
            *(float4*)(a + 4) = *(float4*)(&As[kk][ty * 8 + 4]);
            *(float4*)(b)     = *(float4*)(&Bs[kk][tx * 8]);
            *(float4*)(b + 4) = *(float4*)(&Bs[kk][tx * 8 + 4]);
#pragma unroll
            for (int i = 0; i < 8; i++)
#pragma unroll
                for (int j = 0; j < 8; j++) acc[i][j] += a[i] * b[j];
        }
        __syncthreads();
    }
    float* Cb = (float*)g_B0 + (size_t)by * 128 * DD + bx * 128;
#pragma unroll
    for (int i = 0; i < 8; i++)
#pragma unroll
        for (int j = 0; j < 8; j += 4)
            *(float4*)(&Cb[(ty * 8 + i) * DD + tx * 8 + j]) =
                make_float4(acc[i][j], acc[i][j + 1], acc[i][j + 2], acc[i][j + 3]);
}

// ---------------- GCN aggregation: out = D^-1/2 (A+I) D^-1/2 h + b ---------
// reads g_B0; DST: 0 = g_B1, 1 = g_B2.
// 4 nodes per block; 64 lanes per node, each lane owns 4 dims (float4).
template <bool RELU, int DST>
__global__ void __launch_bounds__(256) k_gcn(const float* __restrict__ bias) {
    const float* h = (const float*)g_B0;
    float* out = (DST == 0) ? (float*)g_B1 : (float*)g_B2;
    int tid  = threadIdx.x;
    int i    = blockIdx.x * 4 + (tid >> 6);   // node
    int d4   = (tid & 63) * 4;                // dim offset
    int beg = g_rowptr[i], end = g_rowptr[i + 1];
    float4 s = make_float4(0.f, 0.f, 0.f, 0.f);
    for (int e = beg; e < end; e++) {
        float c = g_coef[e];
        const float4 v = *(const float4*)&h[(size_t)g_srcidx[e] * DD + d4];
        s.x += c * v.x; s.y += c * v.y; s.z += c * v.z; s.w += c * v.w;
    }
    float di  = g_dinv[i];
    float dii = di * di;
    const float4 hv = *(const float4*)&h[(size_t)i * DD + d4];
    const float4 bv = *(const float4*)&bias[d4];
    float4 r;
    r.x = di * s.x + dii * hv.x + bv.x;
    r.y = di * s.y + dii * hv.y + bv.y;
    r.z = di * s.z + dii * hv.z + bv.z;
    r.w = di * s.w + dii * hv.w + bv.w;
    if (RELU) {
        r.x = fmaxf(r.x, 0.f); r.y = fmaxf(r.y, 0.f);
        r.z = fmaxf(r.z, 0.f); r.w = fmaxf(r.w, 0.f);
    }
    *(float4*)&out[(size_t)i * DD + d4] = r;
}

// ---------------- per-graph segment softmax over node dim (in g_B2) ---------
__global__ void __launch_bounds__(256) k_segsm() {
    int g = blockIdx.x, d = threadIdx.x;
    float* p = (float*)g_B2 + (size_t)g * NPGC * DD + d;
    float m = -1e30f;
    for (int n = 0; n < NPGC; n++) m = fmaxf(m, p[n * DD]);
    float s = 0.f;
    for (int n = 0; n < NPGC; n++) {
        float e = expf(p[n * DD] - m);
        p[n * DD] = e;
        s += e;
    }
    float inv = 1.f / s;
    for (int n = 0; n < NPGC; n++) p[n * DD] *= inv;
}

// ---------------- fused bilinear pooling + classifier + softmax -------------
// per graph: C = A^T X (a2 = g_B2, x2 = g_B1); logits = C.flat @ Wl + bl
__global__ void __launch_bounds__(256) k_final(const float* __restrict__ Wl,
                                               const float* __restrict__ bl,
                                               float* __restrict__ out) {
    __shared__ float As[32][128];
    __shared__ float Xs[32][128];
    __shared__ float red[256];
    int g = blockIdx.x;
    int tid = threadIdx.x;
    int ti = tid >> 4, tj = tid & 15;
    const float* Ag = (const float*)g_B2 + (size_t)g * NPGC * DD;
    const float* Xg = (const float*)g_B1 + (size_t)g * NPGC * DD;
    float acc0 = 0.f, acc1 = 0.f;

    for (int dT = 0; dT < 2; dT++)
        for (int eT = 0; eT < 2; eT++) {
            float c[8][8] = {};
            for (int nc = 0; nc < 4; nc++) {
#pragma unroll
                for (int l = 0; l < 4; l++) {
                    int idx = tid + l * 256;       // 0..1023
                    int row = idx >> 5;            // n 0..31
                    int c4  = (idx & 31) * 4;      // d/e 0..124
                    *(float4*)(&As[row][c4]) =
                        *(const float4*)(Ag + (nc * 32 + row) * DD + dT * 128 + c4);
                    *(float4*)(&Xs[row][c4]) =
                        *(const float4*)(Xg + (nc * 32 + row) * DD + eT * 128 + c4);
                }
                __syncthreads();
#pragma unroll 8
                for (int n = 0; n < 32; n++) {
                    float a[8], x[8];
                    *(float4*)(a)     = *(float4*)(&As[n][ti * 8]);
                    *(float4*)(a + 4) = *(float4*)(&As[n][ti * 8 + 4]);
                    *(float4*)(x)     = *(float4*)(&Xs[n][tj * 8]);
                    *(float4*)(x + 4) = *(float4*)(&Xs[n][tj * 8 + 4]);
#pragma unroll
                    for (int i = 0; i < 8; i++)
#pragma unroll
                        for (int j = 0; j < 8; j++) c[i][j] += a[i] * x[j];
                }
                __syncthreads();
            }
#pragma unroll
            for (int i = 0; i < 8; i++) {
                int dd = dT * 128 + ti * 8 + i;
#pragma unroll
                for (int j = 0; j < 8; j++) {
                    int ee = eT * 128 + tj * 8 + j;
                    int f = dd * DD + ee;
                    float cv = c[i][j];
                    acc0 += cv * __ldg(&Wl[2 * f]);
                    acc1 += cv * __ldg(&Wl[2 * f + 1]);
                }
            }
        }

    red[tid] = acc0;
    __syncthreads();
    for (int s = 128; s > 0; s >>= 1) {
        if (tid < s) red[tid] += red[tid + s];
        __syncthreads();
    }
    float l0 = red[0];
    __syncthreads();
    red[tid] = acc1;
    __syncthreads();
    for (int s = 128; s > 0; s >>= 1) {
        if (tid < s) red[tid] += red[tid + s];
        __syncthreads();
    }
    float l1 = red[0];
    if (tid == 0) {
        l0 += bl[0];
        l1 += bl[1];
        float m = fmaxf(l0, l1);
        float e0 = expf(l0 - m), e1 = expf(l1 - m);
        float inv = 1.f / (e0 + e1);
        out[g * 2 + 0] = e0 * inv;
        out[g * 2 + 1] = e1 * inv;
    }
}

// ---------------- driver ----------------------------------------------------
extern "C" void kernel_launch(void* const* d_in, const int* in_sizes, int n_in,
                              void* d_out, int out_size) {
    const float* x   = (const float*)d_in[0];
    const void*  ei  = d_in[1];            // int32 or int64 — probed on device
    // d_in[2] = batch (contiguous equal-size graphs; unused)
    const float* Wa1 = (const float*)d_in[3];
    const float* ba1 = (const float*)d_in[4];
    const float* Wa2 = (const float*)d_in[5];
    const float* ba2 = (const float*)d_in[6];
    const float* Wx1 = (const float*)d_in[7];
    const float* bx1 = (const float*)d_in[8];
    const float* Wx2 = (const float*)d_in[9];
    const float* bx2 = (const float*)d_in[10];
    const float* Wl  = (const float*)d_in[11];
    const float* bl  = (const float*)d_in[12];
    float* out = (float*)d_out;

    // edge dtype probe + extraction, then CSR build (shared across all convs)
    k_detect<<<1, 256>>>((const long long*)ei);
    k_extract<<<(EE + 255) / 256, 256>>>(ei);
    k_zero<<<(NN + 255) / 256, 256>>>();
    k_count<<<(EE + 255) / 256, 256>>>();
    k_scan<<<1, 1024>>>();
    k_fill<<<(EE + 255) / 256, 256>>>();

    dim3 ggrid(2, 256);

    // a1 = relu(gcn(x, Wa1, ba1)):      B0 = x @ Wa1 ; B1 = agg(B0)
    k_gemm<0><<<ggrid, 256>>>(x, Wa1);
    k_gcn<true, 0><<<NN / 4, 256>>>(ba1);
    // a2 = segsm(gcn(a1, Wa2, ba2)):    B0 = B1 @ Wa2 ; B2 = agg(B0); softmax
    k_gemm<1><<<ggrid, 256>>>(nullptr, Wa2);
    k_gcn<false, 1><<<NN / 4, 256>>>(ba2);
    k_segsm<<<GG, 256>>>();
    // x1 = relu(gcn(x, Wx1, bx1)):      B0 = x @ Wx1 ; B1 = agg(B0)
    k_gemm<0><<<ggrid, 256>>>(x, Wx1);
    k_gcn<true, 0><<<NN / 4, 256>>>(bx1);
    // x2 = relu(gcn(x1, Wx2, bx2)):     B0 = B1 @ Wx2 ; B1 = agg(B0)
    k_gemm<1><<<ggrid, 256>>>(nullptr, Wx2);
    k_gcn<true, 0><<<NN / 4, 256>>>(bx2);
    // bilinear pooling + classifier + softmax (reads B2, B1)
    k_final<<<GG, 256>>>(Wl, bl, out);
}

// round 9
// speedup vs baseline: 1.0071x; 1.0071x over previous
#include <cuda_runtime.h>
#include <math.h>

#define NN   32768
#define GG   256
#define NPGC 128
#define EE   262144
#define DD   256

// ---------------- packed f32x2 helpers (Blackwell FFMA2) --------------------
__device__ __forceinline__ unsigned long long pk2(float lo, float hi) {
    unsigned long long r;
    asm("mov.b64 %0, {%1, %2};" : "=l"(r) : "f"(lo), "f"(hi));
    return r;
}
__device__ __forceinline__ void fma2(unsigned long long& d,
                                     unsigned long long a,
                                     unsigned long long b) {
    asm("fma.rn.f32x2 %0, %1, %2, %0;" : "+l"(d) : "l"(a), "l"(b));
}
__device__ __forceinline__ float2 upk2(unsigned long long v) {
    float2 f;
    asm("mov.b64 {%0, %1}, %2;" : "=f"(f.x), "=f"(f.y) : "l"(v));
    return f;
}

// ---------------- scratch (static device globals; no runtime alloc) --------
__device__ int   g_is64;
__device__ int   g_src[EE];
__device__ int   g_dst[EE];
__device__ int   g_cnt[NN];
__device__ int   g_fill[NN];
__device__ int   g_rowptr[NN + 1];
__device__ int   g_srcidx[EE];
__device__ float g_coef[EE];
__device__ float g_dinv[NN];
__device__ float g_B0[NN * DD];
__device__ float g_B1[NN * DD];
__device__ float g_B2[NN * DD];

// ---------------- edge dtype probe + extraction -----------------------------
// JAX without x64 silently stores "int64" edge_index as int32. Probe: read the
// first 2048 words as int64; genuine int64 node ids are all in [0, NN).
__global__ void k_detect(const long long* __restrict__ ei) {
    __shared__ int ok;
    if (threadIdx.x == 0) ok = 1;
    __syncthreads();
    for (int idx = threadIdx.x; idx < 2048; idx += 256) {
        long long v = ei[idx];
        if (v < 0 || v >= NN) ok = 0;
    }
    __syncthreads();
    if (threadIdx.x == 0) g_is64 = ok;
}

__global__ void k_extract(const void* __restrict__ eiraw) {
    int e = blockIdx.x * blockDim.x + threadIdx.x;
    if (e >= EE) return;
    int src, dst;
    if (g_is64) {
        const long long* p = (const long long*)eiraw;
        src = (int)p[e];
        dst = (int)p[EE + e];
    } else {
        const int* p = (const int*)eiraw;
        src = p[e];
        dst = p[EE + e];
    }
    g_src[e] = src & (NN - 1);
    g_dst[e] = dst & (NN - 1);
}

// ---------------- CSR build -------------------------------------------------
__global__ void k_zero() {
    int i = blockIdx.x * blockDim.x + threadIdx.x;
    if (i < NN) { g_cnt[i] = 0; g_fill[i] = 0; }
}

__global__ void k_count() {
    int e = blockIdx.x * blockDim.x + threadIdx.x;
    if (e < EE) atomicAdd(&g_cnt[g_dst[e]], 1);
}

// single block, 1024 threads, each owns 32 consecutive entries
__global__ void k_scan() {
    __shared__ int ssum[1024];
    int t = threadIdx.x;
    int base = t * 32;
    int loc[32];
    int s = 0;
#pragma unroll
    for (int i = 0; i < 32; i++) {
        int c = g_cnt[base + i];
        loc[i] = s;
        s += c;
        g_dinv[base + i] = rsqrtf((float)c + 1.0f);
    }
    ssum[t] = s;
    __syncthreads();
    for (int off = 1; off < 1024; off <<= 1) {
        int v = 0;
        if (t >= off) v = ssum[t - off];
        __syncthreads();
        if (t >= off) ssum[t] += v;
        __syncthreads();
    }
    int excl = (t == 0) ? 0 : ssum[t - 1];
#pragma unroll
    for (int i = 0; i < 32; i++) g_rowptr[base + i] = excl + loc[i];
    if (t == 1023) g_rowptr[NN] = ssum[1023];
}

__global__ void k_fill() {
    int e = blockIdx.x * blockDim.x + threadIdx.x;
    if (e >= EE) return;
    int src = g_src[e];
    int dst = g_dst[e];
    int pos = g_rowptr[dst] + atomicAdd(&g_fill[dst], 1);
    g_srcidx[pos] = src;
    g_coef[pos]   = g_dinv[src];
}

// ---------------- SGEMM: g_B0[M,256] = A[M,256] @ W[256,256] ----------------
// BM=128, BN=128, BK=16, 256 threads, 8x8 per thread, FFMA2 inner loop
// SRC: 0 = external pointer, 1 = g_B1
template <int SRC>
__global__ void __launch_bounds__(256) k_gemm(const float* __restrict__ Aext,
                                              const float* __restrict__ W) {
    __shared__ float As[16][128];
    __shared__ float Bs[16][128];
    int tid = threadIdx.x;
    int bx = blockIdx.x;              // 0..1  (col tile)
    int by = blockIdx.y;              // 0..255 (row tile)
    int tx = tid & 15, ty = tid >> 4;
    unsigned long long acc2[8][4] = {};   // 8 rows x 4 col-pairs
    const float* A = (SRC == 0) ? Aext : (const float*)g_B1;
    const float* Ab = A + (size_t)by * 128 * DD;
    const float* Wb = W + bx * 128;

    for (int k0 = 0; k0 < DD; k0 += 16) {
#pragma unroll
        for (int l = 0; l < 2; l++) {
            int idx = tid + l * 256;          // 0..511
            int row = idx >> 2;               // 0..127
            int c4  = (idx & 3) * 4;          // 0,4,8,12
            float4 v = *(const float4*)(Ab + row * DD + k0 + c4);
            As[c4 + 0][row] = v.x; As[c4 + 1][row] = v.y;
            As[c4 + 2][row] = v.z; As[c4 + 3][row] = v.w;
        }
#pragma unroll
        for (int l = 0; l < 2; l++) {
            int idx = tid + l * 256;
            int kk = idx >> 5;                // 0..15
            int n4 = (idx & 31) * 4;          // 0..124
            *(float4*)(&Bs[kk][n4]) = *(const float4*)(Wb + (k0 + kk) * DD + n4);
        }
        __syncthreads();
#pragma unroll
        for (int kk = 0; kk < 16; kk++) {
            float a[8];
            *(float4*)(a)     = *(float4*)(&As[kk][ty * 8]);
            *(float4*)(a + 4) = *(float4*)(&As[kk][ty * 8 + 4]);
            ulonglong2 b01 = *(ulonglong2*)(&Bs[kk][tx * 8]);
            ulonglong2 b23 = *(ulonglong2*)(&Bs[kk][tx * 8 + 4]);
            unsigned long long b2[4] = {b01.x, b01.y, b23.x, b23.y};
#pragma unroll
            for (int i = 0; i < 8; i++) {
                unsigned long long a2 = pk2(a[i], a[i]);
#pragma unroll
                for (int p = 0; p < 4; p++) fma2(acc2[i][p], a2, b2[p]);
            }
        }
        __syncthreads();
    }
    float* Cb = (float*)g_B0 + (size_t)by * 128 * DD + bx * 128;
#pragma unroll
    for (int i = 0; i < 8; i++) {
        float2 c0 = upk2(acc2[i][0]);
        float2 c1 = upk2(acc2[i][1]);
        float2 c2 = upk2(acc2[i][2]);
        float2 c3 = upk2(acc2[i][3]);
        *(float4*)(&Cb[(ty * 8 + i) * DD + tx * 8])     = make_float4(c0.x, c0.y, c1.x, c1.y);
        *(float4*)(&Cb[(ty * 8 + i) * DD + tx * 8 + 4]) = make_float4(c2.x, c2.y, c3.x, c3.y);
    }
}

// ---------------- GCN aggregation: out = D^-1/2 (A+I) D^-1/2 h + b ---------
// reads g_B0; DST: 0 = g_B1, 1 = g_B2.
// 4 nodes per block; 64 lanes per node, each lane owns 4 dims (float4).
template <bool RELU, int DST>
__global__ void __launch_bounds__(256) k_gcn(const float* __restrict__ bias) {
    const float* h = (const float*)g_B0;
    float* out = (DST == 0) ? (float*)g_B1 : (float*)g_B2;
    int tid  = threadIdx.x;
    int i    = blockIdx.x * 4 + (tid >> 6);   // node
    int d4   = (tid & 63) * 4;                // dim offset
    int beg = g_rowptr[i], end = g_rowptr[i + 1];
    float4 s = make_float4(0.f, 0.f, 0.f, 0.f);
    for (int e = beg; e < end; e++) {
        float c = g_coef[e];
        const float4 v = *(const float4*)&h[(size_t)g_srcidx[e] * DD + d4];
        s.x += c * v.x; s.y += c * v.y; s.z += c * v.z; s.w += c * v.w;
    }
    float di  = g_dinv[i];
    float dii = di * di;
    const float4 hv = *(const float4*)&h[(size_t)i * DD + d4];
    const float4 bv = *(const float4*)&bias[d4];
    float4 r;
    r.x = di * s.x + dii * hv.x + bv.x;
    r.y = di * s.y + dii * hv.y + bv.y;
    r.z = di * s.z + dii * hv.z + bv.z;
    r.w = di * s.w + dii * hv.w + bv.w;
    if (RELU) {
        r.x = fmaxf(r.x, 0.f); r.y = fmaxf(r.y, 0.f);
        r.z = fmaxf(r.z, 0.f); r.w = fmaxf(r.w, 0.f);
    }
    *(float4*)&out[(size_t)i * DD + d4] = r;
}

// ---------------- per-graph segment softmax over node dim (in g_B2) ---------
__global__ void __launch_bounds__(256) k_segsm() {
    int g = blockIdx.x, d = threadIdx.x;
    float* p = (float*)g_B2 + (size_t)g * NPGC * DD + d;
    float m = -1e30f;
    for (int n = 0; n < NPGC; n++) m = fmaxf(m, p[n * DD]);
    float s = 0.f;
    for (int n = 0; n < NPGC; n++) {
        float e = expf(p[n * DD] - m);
        p[n * DD] = e;
        s += e;
    }
    float inv = 1.f / s;
    for (int n = 0; n < NPGC; n++) p[n * DD] *= inv;
}

// ---------------- fused bilinear pooling + classifier + softmax -------------
// per graph: C = A^T X (a2 = g_B2, x2 = g_B1); logits = C.flat @ Wl + bl
__global__ void __launch_bounds__(256) k_final(const float* __restrict__ Wl,
                                               const float* __restrict__ bl,
                                               float* __restrict__ out) {
    __shared__ float As[32][128];
    __shared__ float Xs[32][128];
    __shared__ float red[256];
    int g = blockIdx.x;
    int tid = threadIdx.x;
    int ti = tid >> 4, tj = tid & 15;
    const float* Ag = (const float*)g_B2 + (size_t)g * NPGC * DD;
    const float* Xg = (const float*)g_B1 + (size_t)g * NPGC * DD;
    float acc0 = 0.f, acc1 = 0.f;

    for (int dT = 0; dT < 2; dT++)
        for (int eT = 0; eT < 2; eT++) {
            unsigned long long c2[8][4] = {};
            for (int nc = 0; nc < 4; nc++) {
#pragma unroll
                for (int l = 0; l < 4; l++) {
                    int idx = tid + l * 256;       // 0..1023
                    int row = idx >> 5;            // n 0..31
                    int c4  = (idx & 31) * 4;      // d/e 0..124
                    *(float4*)(&As[row][c4]) =
                        *(const float4*)(Ag + (nc * 32 + row) * DD + dT * 128 + c4);
                    *(float4*)(&Xs[row][c4]) =
                        *(const float4*)(Xg + (nc * 32 + row) * DD + eT * 128 + c4);
                }
                __syncthreads();
#pragma unroll 8
                for (int n = 0; n < 32; n++) {
                    float a[8];
                    *(float4*)(a)     = *(float4*)(&As[n][ti * 8]);
                    *(float4*)(a + 4) = *(float4*)(&As[n][ti * 8 + 4]);
                    ulonglong2 x01 = *(ulonglong2*)(&Xs[n][tj * 8]);
                    ulonglong2 x23 = *(ulonglong2*)(&Xs[n][tj * 8 + 4]);
                    unsigned long long xp[4] = {x01.x, x01.y, x23.x, x23.y};
#pragma unroll
                    for (int i = 0; i < 8; i++) {
                        unsigned long long a2 = pk2(a[i], a[i]);
#pragma unroll
                        for (int p = 0; p < 4; p++) fma2(c2[i][p], a2, xp[p]);
                    }
                }
                __syncthreads();
            }
            // fold C tile into logits via Wl
#pragma unroll
            for (int i = 0; i < 8; i++) {
                int dd = dT * 128 + ti * 8 + i;
#pragma unroll
                for (int p = 0; p < 4; p++) {
                    float2 cv = upk2(c2[i][p]);
                    int ee = eT * 128 + tj * 8 + p * 2;
                    int f0 = dd * DD + ee;
                    acc0 += cv.x * __ldg(&Wl[2 * f0]);
                    acc1 += cv.x * __ldg(&Wl[2 * f0 + 1]);
                    acc0 += cv.y * __ldg(&Wl[2 * (f0 + 1)]);
                    acc1 += cv.y * __ldg(&Wl[2 * (f0 + 1) + 1]);
                }
            }
        }

    red[tid] = acc0;
    __syncthreads();
    for (int s = 128; s > 0; s >>= 1) {
        if (tid < s) red[tid] += red[tid + s];
        __syncthreads();
    }
    float l0 = red[0];
    __syncthreads();
    red[tid] = acc1;
    __syncthreads();
    for (int s = 128; s > 0; s >>= 1) {
        if (tid < s) red[tid] += red[tid + s];
        __syncthreads();
    }
    float l1 = red[0];
    if (tid == 0) {
        l0 += bl[0];
        l1 += bl[1];
        float m = fmaxf(l0, l1);
        float e0 = expf(l0 - m), e1 = expf(l1 - m);
        float inv = 1.f / (e0 + e1);
        out[g * 2 + 0] = e0 * inv;
        out[g * 2 + 1] = e1 * inv;
    }
}

// ---------------- driver ----------------------------------------------------
extern "C" void kernel_launch(void* const* d_in, const int* in_sizes, int n_in,
                              void* d_out, int out_size) {
    const float* x   = (const float*)d_in[0];
    const void*  ei  = d_in[1];            // int32 or int64 — probed on device
    // d_in[2] = batch (contiguous equal-size graphs; unused)
    const float* Wa1 = (const float*)d_in[3];
    const float* ba1 = (const float*)d_in[4];
    const float* Wa2 = (const float*)d_in[5];
    const float* ba2 = (const float*)d_in[6];
    const float* Wx1 = (const float*)d_in[7];
    const float* bx1 = (const float*)d_in[8];
    const float* Wx2 = (const float*)d_in[9];
    const float* bx2 = (const float*)d_in[10];
    const float* Wl  = (const float*)d_in[11];
    const float* bl  = (const float*)d_in[12];
    float* out = (float*)d_out;

    // edge dtype probe + extraction, then CSR build (shared across all convs)
    k_detect<<<1, 256>>>((const long long*)ei);
    k_extract<<<(EE + 255) / 256, 256>>>(ei);
    k_zero<<<(NN + 255) / 256, 256>>>();
    k_count<<<(EE + 255) / 256, 256>>>();
    k_scan<<<1, 1024>>>();
    k_fill<<<(EE + 255) / 256, 256>>>();

    dim3 ggrid(2, 256);

    // a1 = relu(gcn(x, Wa1, ba1)):      B0 = x @ Wa1 ; B1 = agg(B0)
    k_gemm<0><<<ggrid, 256>>>(x, Wa1);
    k_gcn<true, 0><<<NN / 4, 256>>>(ba1);
    // a2 = segsm(gcn(a1, Wa2, ba2)):    B0 = B1 @ Wa2 ; B2 = agg(B0); softmax
    k_gemm<1><<<ggrid, 256>>>(nullptr, Wa2);
    k_gcn<false, 1><<<NN / 4, 256>>>(ba2);
    k_segsm<<<GG, 256>>>();
    // x1 = relu(gcn(x, Wx1, bx1)):      B0 = x @ Wx1 ; B1 = agg(B0)
    k_gemm<0><<<ggrid, 256>>>(x, Wx1);
    k_gcn<true, 0><<<NN / 4, 256>>>(bx1);
    // x2 = relu(gcn(x1, Wx2, bx2)):     B0 = B1 @ Wx2 ; B1 = agg(B0)
    k_gemm<1><<<ggrid, 256>>>(nullptr, Wx2);
    k_gcn<true, 0><<<NN / 4, 256>>>(bx2);
    // bilinear pooling + classifier + softmax (reads B2, B1)
    k_final<<<GG, 256>>>(Wl, bl, out);
}

// round 16
// speedup vs baseline: 1.1818x; 1.1736x over previous
#include <cuda_runtime.h>
#include <cuda_bf16.h>
#include <math.h>

#define NN   32768
#define GG   256
#define NPGC 128
#define EE   262144
#define DD   256

// ---------------- packed f32x2 helpers (k_final) ----------------------------
__device__ __forceinline__ unsigned long long pk2(float lo, float hi) {
    unsigned long long r;
    asm("mov.b64 %0, {%1, %2};" : "=l"(r) : "f"(lo), "f"(hi));
    return r;
}
__device__ __forceinline__ void fma2(unsigned long long& d,
                                     unsigned long long a,
                                     unsigned long long b) {
    asm("fma.rn.f32x2 %0, %1, %2, %0;" : "+l"(d) : "l"(a), "l"(b));
}
__device__ __forceinline__ float2 upk2(unsigned long long v) {
    float2 f;
    asm("mov.b64 {%0, %1}, %2;" : "=f"(f.x), "=f"(f.y) : "l"(v));
    return f;
}

// ---------------- warp-MMA helpers (baseline PTX, compiles for sm_103) ------
__device__ __forceinline__ unsigned smem_u32(const void* p) {
    unsigned a;
    asm("{ .reg .u64 t; cvta.to.shared.u64 t, %1; cvt.u32.u64 %0, t; }"
        : "=r"(a) : "l"(p));
    return a;
}
__device__ __forceinline__ void ldmx4(unsigned addr, unsigned* r) {
    asm volatile("ldmatrix.sync.aligned.m8n8.x4.shared.b16 {%0,%1,%2,%3}, [%4];"
                 : "=r"(r[0]), "=r"(r[1]), "=r"(r[2]), "=r"(r[3]) : "r"(addr));
}
__device__ __forceinline__ void mma16816(float* c, const unsigned* a,
                                         const unsigned* b) {
    asm volatile(
        "mma.sync.aligned.m16n8k16.row.col.f32.bf16.bf16.f32 "
        "{%0,%1,%2,%3}, {%4,%5,%6,%7}, {%8,%9}, {%0,%1,%2,%3};"
        : "+f"(c[0]), "+f"(c[1]), "+f"(c[2]), "+f"(c[3])
        : "r"(a[0]), "r"(a[1]), "r"(a[2]), "r"(a[3]), "r"(b[0]), "r"(b[1]));
}

// ---------------- scratch (static device globals; no runtime alloc) --------
__device__ int   g_is64;
__device__ int   g_src[EE];
__device__ int   g_dst[EE];
__device__ int   g_cnt[NN];
__device__ int   g_fill[NN];
__device__ int   g_rowptr[NN + 1];
__device__ int   g_srcidx[EE];
__device__ float g_coef[EE];
__device__ float g_dinv[NN];
__device__ float g_B0[NN * DD];
__device__ float g_B1[NN * DD];
__device__ float g_B2[NN * DD];
__device__ __nv_bfloat16 g_Wt[4 * 2 * 65536];   // [layer][hi/lo][n][k]

// ---------------- edge dtype probe + extraction -----------------------------
__global__ void k_detect(const long long* __restrict__ ei) {
    __shared__ int ok;
    if (threadIdx.x == 0) ok = 1;
    __syncthreads();
    for (int idx = threadIdx.x; idx < 2048; idx += 256) {
        long long v = ei[idx];
        if (v < 0 || v >= NN) ok = 0;
    }
    __syncthreads();
    if (threadIdx.x == 0) g_is64 = ok;
}

__global__ void k_extract(const void* __restrict__ eiraw) {
    int e = blockIdx.x * blockDim.x + threadIdx.x;
    if (e >= EE) return;
    int src, dst;
    if (g_is64) {
        const long long* p = (const long long*)eiraw;
        src = (int)p[e];
        dst = (int)p[EE + e];
    } else {
        const int* p = (const int*)eiraw;
        src = p[e];
        dst = p[EE + e];
    }
    g_src[e] = src & (NN - 1);
    g_dst[e] = dst & (NN - 1);
}

// ---------------- CSR build -------------------------------------------------
__global__ void k_zero() {
    int i = blockIdx.x * blockDim.x + threadIdx.x;
    if (i < NN) { g_cnt[i] = 0; g_fill[i] = 0; }
}

__global__ void k_count() {
    int e = blockIdx.x * blockDim.x + threadIdx.x;
    if (e < EE) atomicAdd(&g_cnt[g_dst[e]], 1);
}

__global__ void k_scan() {
    __shared__ int ssum[1024];
    int t = threadIdx.x;
    int base = t * 32;
    int loc[32];
    int s = 0;
#pragma unroll
    for (int i = 0; i < 32; i++) {
        int c = g_cnt[base + i];
        loc[i] = s;
        s += c;
        g_dinv[base + i] = rsqrtf((float)c + 1.0f);
    }
    ssum[t] = s;
    __syncthreads();
    for (int off = 1; off < 1024; off <<= 1) {
        int v = 0;
        if (t >= off) v = ssum[t - off];
        __syncthreads();
        if (t >= off) ssum[t] += v;
        __syncthreads();
    }
    int excl = (t == 0) ? 0 : ssum[t - 1];
#pragma unroll
    for (int i = 0; i < 32; i++) g_rowptr[base + i] = excl + loc[i];
    if (t == 1023) g_rowptr[NN] = ssum[1023];
}

__global__ void k_fill() {
    int e = blockIdx.x * blockDim.x + threadIdx.x;
    if (e >= EE) return;
    int src = g_src[e];
    int dst = g_dst[e];
    int pos = g_rowptr[dst] + atomicAdd(&g_fill[dst], 1);
    g_srcidx[pos] = src;
    g_coef[pos]   = g_dinv[src];
}

// ---------------- weight convert: W[k][n] fp32 -> g_Wt[l][hi/lo][n][k] bf16 --
__global__ void k_wconv(const float* __restrict__ W0, const float* __restrict__ W1,
                        const float* __restrict__ W2, const float* __restrict__ W3) {
    int idx = blockIdx.x * 256 + threadIdx.x;   // 32768 total
    int l  = idx >> 13;
    int r  = idx & 8191;
    int n  = r >> 5;
    int kg = r & 31;
    const float* W = (l == 0) ? W0 : (l == 1) ? W1 : (l == 2) ? W2 : W3;
    __align__(16) __nv_bfloat16 hi[8], lo[8];
#pragma unroll
    for (int i = 0; i < 8; i++) {
        float a = W[(kg * 8 + i) * 256 + n];
        __nv_bfloat16 h = __float2bfloat16(a);
        hi[i] = h;
        lo[i] = __float2bfloat16(a - __bfloat162float(h));
    }
    size_t base = (size_t)(l * 2) * 65536 + (size_t)n * 256 + kg * 8;
    *(uint4*)&g_Wt[base]         = *(uint4*)hi;
    *(uint4*)&g_Wt[base + 65536] = *(uint4*)lo;
}

// ---------------- split-bf16 HMMA GEMM: g_B0[M,256] = A @ W ------------------
// CTA tile 128x128 (bx 0/1), 8 warps (4x2), warp tile 32x64, K chunks of 64.
// smem rows padded to 72 bf16 (144 B: 16B-aligned, conflict-free ldmatrix).
#define HS_STRIDE 72
#define HS_TILE   (128 * HS_STRIDE * 2)    // 18432 bytes
#define HG_SMEM   (4 * HS_TILE)            // 73728: Ahi | Alo | Bhi | Blo
template <int SRC>
__global__ void __launch_bounds__(256) k_hgemm(const float* __restrict__ Aext,
                                               int layer) {
    extern __shared__ char smem[];
    const int A_HI = 0, A_LO = HS_TILE, B_HI = 2 * HS_TILE, B_LO = 3 * HS_TILE;
    const float* A = (SRC == 0) ? Aext : (const float*)g_B1;
    unsigned sb = smem_u32(smem);
    int tid = threadIdx.x, lane = tid & 31, wid = tid >> 5;
    int wr = wid & 3, wc = wid >> 2;           // warp row(4)/col(2)
    int bx = blockIdx.x, by = blockIdx.y;
    const __nv_bfloat16* Wh = g_Wt + (size_t)(layer * 2) * 65536;
    const __nv_bfloat16* Wl = Wh + 65536;

    float acc[2][8][4] = {};
    int g4 = lane >> 2, tig = lane & 3;        // mma group / thread-in-group

    for (int c = 0; c < 4; c++) {              // K chunk of 64
        int k0 = c * 64;
        // A: 128 rows x 64 k fp32 -> bf16 hi/lo, padded rows
        for (int g = tid; g < 1024; g += 256) {
            int row = g >> 3, kg = g & 7;
            const float* src = A + (size_t)(by * 128 + row) * DD + k0 + kg * 8;
            float4 v0 = *(const float4*)(src);
            float4 v1 = *(const float4*)(src + 4);
            float a[8] = {v0.x, v0.y, v0.z, v0.w, v1.x, v1.y, v1.z, v1.w};
            __align__(16) __nv_bfloat16 hb[8], lb[8];
#pragma unroll
            for (int i = 0; i < 8; i++) {
                __nv_bfloat16 h = __float2bfloat16(a[i]);
                hb[i] = h;
                lb[i] = __float2bfloat16(a[i] - __bfloat162float(h));
            }
            unsigned off = (unsigned)(row * HS_STRIDE + kg * 8) * 2;
            *(uint4*)(smem + A_HI + off) = *(uint4*)hb;
            *(uint4*)(smem + A_LO + off) = *(uint4*)lb;
        }
        // B: 128 n-rows x 64 k bf16 from pre-converted g_Wt
        for (int g = tid; g < 1024; g += 256) {
            int n = g >> 3, kg = g & 7;
            size_t so = (size_t)(bx * 128 + n) * 256 + k0 + kg * 8;
            unsigned off = (unsigned)(n * HS_STRIDE + kg * 8) * 2;
            *(uint4*)(smem + B_HI + off) = *(const uint4*)(Wh + so);
            *(uint4*)(smem + B_LO + off) = *(const uint4*)(Wl + so);
        }
        __syncthreads();
#pragma unroll
        for (int ks = 0; ks < 4; ks++) {       // k16 steps within chunk
            int kb = ks * 16;
            // A fragments: 2 m-tiles, hi+lo  (lane%16 -> row, lane/16 -> k half)
            unsigned ahi[2][4], alo[2][4];
#pragma unroll
            for (int mt = 0; mt < 2; mt++) {
                int rowb = wr * 32 + mt * 16;
                unsigned off = (unsigned)((rowb + (lane & 15)) * HS_STRIDE +
                                          kb + (lane >> 4) * 8) * 2;
                ldmx4(sb + A_HI + off, ahi[mt]);
                ldmx4(sb + A_LO + off, alo[mt]);
            }
            // B fragments: 4 n16-pairs, hi+lo
            unsigned bhi[4][4], blo[4][4];
            int n_off = (lane & 7) + ((lane >> 4) << 3);
            int k_off = ((lane >> 3) & 1) * 8;
#pragma unroll
            for (int np = 0; np < 4; np++) {
                int nb = wc * 64 + np * 16;
                unsigned off = (unsigned)((nb + n_off) * HS_STRIDE +
                                          kb + k_off) * 2;
                ldmx4(sb + B_HI + off, bhi[np]);
                ldmx4(sb + B_LO + off, blo[np]);
            }
#pragma unroll
            for (int mt = 0; mt < 2; mt++)
#pragma unroll
                for (int nt = 0; nt < 8; nt++) {
                    int np = nt >> 1, sub = (nt & 1) * 2;
                    mma16816(acc[mt][nt], ahi[mt], &bhi[np][sub]);
                    mma16816(acc[mt][nt], ahi[mt], &blo[np][sub]);
                    mma16816(acc[mt][nt], alo[mt], &bhi[np][sub]);
                }
        }
        __syncthreads();
    }
    // epilogue: C fragment rows g4/g4+8, cols tig*2..+1
#pragma unroll
    for (int mt = 0; mt < 2; mt++)
#pragma unroll
        for (int nt = 0; nt < 8; nt++) {
            int grow = by * 128 + wr * 32 + mt * 16 + g4;
            int gcol = bx * 128 + wc * 64 + nt * 8 + tig * 2;
            float* C = (float*)g_B0;
            *(float2*)&C[(size_t)grow * DD + gcol] =
                make_float2(acc[mt][nt][0], acc[mt][nt][1]);
            *(float2*)&C[(size_t)(grow + 8) * DD + gcol] =
                make_float2(acc[mt][nt][2], acc[mt][nt][3]);
        }
}

// ---------------- GCN aggregation: out = D^-1/2 (A+I) D^-1/2 h + b ---------
template <bool RELU, int DST>
__global__ void __launch_bounds__(256) k_gcn(const float* __restrict__ bias) {
    const float* h = (const float*)g_B0;
    float* out = (DST == 0) ? (float*)g_B1 : (float*)g_B2;
    int tid  = threadIdx.x;
    int i    = blockIdx.x * 4 + (tid >> 6);
    int d4   = (tid & 63) * 4;
    int beg = g_rowptr[i], end = g_rowptr[i + 1];
    float4 s = make_float4(0.f, 0.f, 0.f, 0.f);
    for (int e = beg; e < end; e++) {
        float c = g_coef[e];
        const float4 v = *(const float4*)&h[(size_t)g_srcidx[e] * DD + d4];
        s.x += c * v.x; s.y += c * v.y; s.z += c * v.z; s.w += c * v.w;
    }
    float di  = g_dinv[i];
    float dii = di * di;
    const float4 hv = *(const float4*)&h[(size_t)i * DD + d4];
    const float4 bv = *(const float4*)&bias[d4];
    float4 r;
    r.x = di * s.x + dii * hv.x + bv.x;
    r.y = di * s.y + dii * hv.y + bv.y;
    r.z = di * s.z + dii * hv.z + bv.z;
    r.w = di * s.w + dii * hv.w + bv.w;
    if (RELU) {
        r.x = fmaxf(r.x, 0.f); r.y = fmaxf(r.y, 0.f);
        r.z = fmaxf(r.z, 0.f); r.w = fmaxf(r.w, 0.f);
    }
    *(float4*)&out[(size_t)i * DD + d4] = r;
}

// ---------------- per-graph segment softmax over node dim (in g_B2) ---------
__global__ void __launch_bounds__(256) k_segsm() {
    int g = blockIdx.x, d = threadIdx.x;
    float* p = (float*)g_B2 + (size_t)g * NPGC * DD + d;
    float m = -1e30f;
    for (int n = 0; n < NPGC; n++) m = fmaxf(m, p[n * DD]);
    float s = 0.f;
    for (int n = 0; n < NPGC; n++) {
        float e = expf(p[n * DD] - m);
        p[n * DD] = e;
        s += e;
    }
    float inv = 1.f / s;
    for (int n = 0; n < NPGC; n++) p[n * DD] *= inv;
}

// ---------------- fused bilinear pooling + classifier + softmax -------------
__global__ void __launch_bounds__(256) k_final(const float* __restrict__ Wl,
                                               const float* __restrict__ bl,
                                               float* __restrict__ out) {
    __shared__ float As[32][128];
    __shared__ float Xs[32][128];
    __shared__ float red[256];
    int g = blockIdx.x;
    int tid = threadIdx.x;
    int ti = tid >> 4, tj = tid & 15;
    const float* Ag = (const float*)g_B2 + (size_t)g * NPGC * DD;
    const float* Xg = (const float*)g_B1 + (size_t)g * NPGC * DD;
    float acc0 = 0.f, acc1 = 0.f;

    for (int dT = 0; dT < 2; dT++)
        for (int eT = 0; eT < 2; eT++) {
            unsigned long long c2[8][4] = {};
            for (int nc = 0; nc < 4; nc++) {
#pragma unroll
                for (int l = 0; l < 4; l++) {
                    int idx = tid + l * 256;
                    int row = idx >> 5;
                    int c4  = (idx & 31) * 4;
                    *(float4*)(&As[row][c4]) =
                        *(const float4*)(Ag + (nc * 32 + row) * DD + dT * 128 + c4);
                    *(float4*)(&Xs[row][c4]) =
                        *(const float4*)(Xg + (nc * 32 + row) * DD + eT * 128 + c4);
                }
                __syncthreads();
#pragma unroll 8
                for (int n = 0; n < 32; n++) {
                    float a[8];
                    *(float4*)(a)     = *(float4*)(&As[n][ti * 8]);
                    *(float4*)(a + 4) = *(float4*)(&As[n][ti * 8 + 4]);
                    ulonglong2 x01 = *(ulonglong2*)(&Xs[n][tj * 8]);
                    ulonglong2 x23 = *(ulonglong2*)(&Xs[n][tj * 8 + 4]);
                    unsigned long long xp[4] = {x01.x, x01.y, x23.x, x23.y};
#pragma unroll
                    for (int i = 0; i < 8; i++) {
                        unsigned long long a2 = pk2(a[i], a[i]);
#pragma unroll
                        for (int p = 0; p < 4; p++) fma2(c2[i][p], a2, xp[p]);
                    }
                }
                __syncthreads();
            }
#pragma unroll
            for (int i = 0; i < 8; i++) {
                int dd = dT * 128 + ti * 8 + i;
#pragma unroll
                for (int p = 0; p < 4; p++) {
                    float2 cv = upk2(c2[i][p]);
                    int ee = eT * 128 + tj * 8 + p * 2;
                    int f0 = dd * DD + ee;
                    acc0 += cv.x * __ldg(&Wl[2 * f0]);
                    acc1 += cv.x * __ldg(&Wl[2 * f0 + 1]);
                    acc0 += cv.y * __ldg(&Wl[2 * (f0 + 1)]);
                    acc1 += cv.y * __ldg(&Wl[2 * (f0 + 1) + 1]);
                }
            }
        }

    red[tid] = acc0;
    __syncthreads();
    for (int s = 128; s > 0; s >>= 1) {
        if (tid < s) red[tid] += red[tid + s];
        __syncthreads();
    }
    float l0 = red[0];
    __syncthreads();
    red[tid] = acc1;
    __syncthreads();
    for (int s = 128; s > 0; s >>= 1) {
        if (tid < s) red[tid] += red[tid + s];
        __syncthreads();
    }
    float l1 = red[0];
    if (tid == 0) {
        l0 += bl[0];
        l1 += bl[1];
        float m = fmaxf(l0, l1);
        float e0 = expf(l0 - m), e1 = expf(l1 - m);
        float inv = 1.f / (e0 + e1);
        out[g * 2 + 0] = e0 * inv;
        out[g * 2 + 1] = e1 * inv;
    }
}

// ---------------- driver ----------------------------------------------------
extern "C" void kernel_launch(void* const* d_in, const int* in_sizes, int n_in,
                              void* d_out, int out_size) {
    const float* x   = (const float*)d_in[0];
    const void*  ei  = d_in[1];
    const float* Wa1 = (const float*)d_in[3];
    const float* ba1 = (const float*)d_in[4];
    const float* Wa2 = (const float*)d_in[5];
    const float* ba2 = (const float*)d_in[6];
    const float* Wx1 = (const float*)d_in[7];
    const float* bx1 = (const float*)d_in[8];
    const float* Wx2 = (const float*)d_in[9];
    const float* bx2 = (const float*)d_in[10];
    const float* Wl  = (const float*)d_in[11];
    const float* bl  = (const float*)d_in[12];
    float* out = (float*)d_out;

    cudaFuncSetAttribute(k_hgemm<0>, cudaFuncAttributeMaxDynamicSharedMemorySize, HG_SMEM);
    cudaFuncSetAttribute(k_hgemm<1>, cudaFuncAttributeMaxDynamicSharedMemorySize, HG_SMEM);

    // edge dtype probe + extraction, then CSR build
    k_detect<<<1, 256>>>((const long long*)ei);
    k_extract<<<(EE + 255) / 256, 256>>>(ei);
    k_zero<<<(NN + 255) / 256, 256>>>();
    k_count<<<(EE + 255) / 256, 256>>>();
    k_scan<<<1, 1024>>>();
    k_fill<<<(EE + 255) / 256, 256>>>();
    // weights -> bf16 hi/lo transposed (full 256x256 per layer)
    k_wconv<<<128, 256>>>(Wa1, Wa2, Wx1, Wx2);

    dim3 hgrid(2, 256);

    // a1 = relu(gcn(x, Wa1, ba1)):      B0 = x @ Wa1 ; B1 = agg(B0)
    k_hgemm<0><<<hgrid, 256, HG_SMEM>>>(x, 0);
    k_gcn<true, 0><<<NN / 4, 256>>>(ba1);
    // a2 = segsm(gcn(a1, Wa2, ba2)):    B0 = B1 @ Wa2 ; B2 = agg(B0); softmax
    k_hgemm<1><<<hgrid, 256, HG_SMEM>>>(nullptr, 1);
    k_gcn<false, 1><<<NN / 4, 256>>>(ba2);
    k_segsm<<<GG, 256>>>();
    // x1 = relu(gcn(x, Wx1, bx1)):      B0 = x @ Wx1 ; B1 = agg(B0)
    k_hgemm<0><<<hgrid, 256, HG_SMEM>>>(x, 2);
    k_gcn<true, 0><<<NN / 4, 256>>>(bx1);
    // x2 = relu(gcn(x1, Wx2, bx2)):     B0 = B1 @ Wx2 ; B1 = agg(B0)
    k_hgemm<1><<<hgrid, 256, HG_SMEM>>>(nullptr, 3);
    k_gcn<true, 0><<<NN / 4, 256>>>(bx2);
    // bilinear pooling + classifier + softmax (reads B2, B1)
    k_final<<<GG, 256>>>(Wl, bl, out);
}